// round 4
// baseline (speedup 1.0000x reference)
#include <cuda_runtime.h>

#define FULLMASK 0xffffffffu

// ---- packed-f32x2 helpers (FFMA2 path: only reachable via explicit PTX) ----
__device__ __forceinline__ unsigned long long pk2(float v) {
    unsigned long long d; unsigned int b = __float_as_uint(v);
    asm("mov.b64 %0, {%1, %1};" : "=l"(d) : "r"(b));
    return d;
}
__device__ __forceinline__ void upk2(unsigned long long p, float& lo, float& hi) {
    unsigned int a, b;
    asm("mov.b64 {%0, %1}, %2;" : "=r"(a), "=r"(b) : "l"(p));
    lo = __uint_as_float(a); hi = __uint_as_float(b);
}
__device__ __forceinline__ unsigned long long ffma2(unsigned long long a,
                                                    unsigned long long b,
                                                    unsigned long long c) {
    unsigned long long d;
    asm("fma.rn.f32x2 %0, %1, %2, %3;" : "=l"(d) : "l"(a), "l"(b), "l"(c));
    return d;
}

// ---- weights in constant memory, pre-shaped as 16B vectors of packed pairs ----
__constant__ ulonglong2 cW1p[56];    // W1 (7,32) = 224 floats
__constant__ ulonglong2 cB1p[8];     // b1 (32,)
__constant__ ulonglong2 cW2p[512];   // W2 (64,32) = 2048 floats (rows 0..31 used here)
__constant__ float      cW3s[32];
__constant__ float      cB3[1];

// ---- packed per-point data: [pos.xyz, stddev][norm.xyz, 0] = one 32B sector ----
__device__ float4 g_packed[2 * 50048];

__global__ __launch_bounds__(256) void pack_kernel(
    const float* __restrict__ pos,
    const float* __restrict__ normals,
    const float* __restrict__ stddev,
    int N)
{
    int i = blockIdx.x * 256 + threadIdx.x;
    if (i >= N) return;
    float4 a, b;
    a.x = pos[3*i+0]; a.y = pos[3*i+1]; a.z = pos[3*i+2]; a.w = stddev[i];
    b.x = normals[3*i+0]; b.y = normals[3*i+1]; b.z = normals[3*i+2]; b.w = 0.0f;
    g_packed[2*i+0] = a;
    g_packed[2*i+1] = b;
}

__global__ __launch_bounds__(256, 2) void normal_est_kernel(
    const float* __restrict__ old_w,    // N*32
    const int*   __restrict__ dense_l,  // N*32
    const float* __restrict__ W2g,      // (64,32) global, for sW2bT fill
    const float* __restrict__ b2g,      // (32,)
    float* __restrict__ out_normals,    // N*3
    float* __restrict__ out_weights,    // N*32
    int N)
{
    __shared__ float sH[8][32][33];   // per-warp h transpose, pad-33 conflict-free
    __shared__ float sW2bT[32][33];   // [j][m] = W2[32+m][j]  (lane-varying reads)
    __shared__ float sG[8][32];
    __shared__ __align__(16) float sGw[8][32];

    const int tid  = threadIdx.x;
    const int lane = tid & 31;
    const int warp = tid >> 5;

    for (int idx = tid; idx < 1024; idx += 256) {
        int m = idx >> 5, j = idx & 31;            // W2 row (32+m), col j
        sW2bT[j][m] = W2g[(32 + m) * 32 + j];
    }
    __syncthreads();

    const int i = blockIdx.x * 8 + warp;
    if (i >= N) return;

    // ---- gather (packed: 2 LDG.128 per neighbor, 1 sector) ----
    const int nb = dense_l[i * 32 + lane];

    const float4 ci = g_packed[2*i+0];
    const float4 ni = g_packed[2*i+1];
    const float4 cj = g_packed[2*nb+0];
    const float4 nj = g_packed[2*nb+1];

    const float dcx = cj.x - ci.x, dcy = cj.y - ci.y, dcz = cj.z - ci.z;
    const float invsd = 1.0f / ci.w;
    const float dx = dcx * invsd, dy = dcy * invsd, dz = dcz * invsd;
    const float wo = old_w[i * 32 + lane];
    const float f4 = fabsf(dx*ni.x + dy*ni.y + dz*ni.z);
    const float f5 = fabsf(dx*nj.x + dy*nj.y + dz*nj.z);
    const float f6 = fabsf(ni.x*nj.x + ni.y*nj.y + ni.z*nj.z);

    float f[7];
    f[0] = dx; f[1] = dy; f[2] = dz; f[3] = wo; f[4] = f4; f[5] = f5; f[6] = f6;

    // ---- layer 1 (packed): h = relu(f @ W1 + b1), 112 FFMA2 ----
    unsigned long long hp[16];
#pragma unroll
    for (int k = 0; k < 8; ++k) {
        const ulonglong2 q = cB1p[k];
        hp[2*k+0] = q.x; hp[2*k+1] = q.y;
    }
#pragma unroll
    for (int in = 0; in < 7; ++in) {
        const unsigned long long fp = pk2(f[in]);
#pragma unroll
        for (int k = 0; k < 8; ++k) {
            const ulonglong2 w = cW1p[in * 8 + k];
            hp[2*k+0] = ffma2(fp, w.x, hp[2*k+0]);
            hp[2*k+1] = ffma2(fp, w.y, hp[2*k+1]);
        }
    }
    float h[32];
#pragma unroll
    for (int p = 0; p < 16; ++p) upk2(hp[p], h[2*p+0], h[2*p+1]);
#pragma unroll
    for (int j = 0; j < 32; ++j) h[j] = fmaxf(h[j], 0.0f);

    // ---- segment max via shared transpose ----
#pragma unroll
    for (int j = 0; j < 32; ++j) sH[warp][j][lane] = h[j];
    __syncwarp();
    float g = sH[warp][lane][0];
#pragma unroll
    for (int e = 1; e < 32; ++e) g = fmaxf(g, sH[warp][lane][e]);

    // ---- shared half of layer 2: gw = b2 + g @ W2[32:64]  (once/point) ----
    sG[warp][lane] = g;
    __syncwarp();
    float gw = b2g[lane];
#pragma unroll
    for (int m = 0; m < 32; ++m)
        gw = fmaf(sG[warp][m], sW2bT[lane][m], gw);
    sGw[warp][lane] = gw;
    __syncwarp();

    // ---- layer 2 per-edge (packed): 512 FFMA2, accum pairs (2p,2p+1) ----
    unsigned long long ap[16];
    const unsigned long long* gwp = (const unsigned long long*)&sGw[warp][0];
#pragma unroll
    for (int p = 0; p < 16; ++p) ap[p] = gwp[p];   // LDS.64 broadcast pairs
#pragma unroll
    for (int m = 0; m < 32; ++m) {
        const unsigned long long hm2 = pk2(h[m]);
#pragma unroll
        for (int k = 0; k < 8; ++k) {
            const ulonglong2 w = cW2p[m * 8 + k];
            ap[2*k+0] = ffma2(hm2, w.x, ap[2*k+0]);
            ap[2*k+1] = ffma2(hm2, w.y, ap[2*k+1]);
        }
    }

    // ---- layer 3 ----
    float s3 = 0.0f;
#pragma unroll
    for (int p = 0; p < 16; ++p) {
        float a, b;
        upk2(ap[p], a, b);
        s3 = fmaf(fmaxf(a, 0.0f), cW3s[2*p+0], s3);
        s3 = fmaf(fmaxf(b, 0.0f), cW3s[2*p+1], s3);
    }
    const float wgt = 1.0f / (1.0f + __expf(-(s3 + cB3[0])));

    out_weights[i * 32 + lane] = wgt;

    // ---- weighted covariance (unscaled dc), 6-term butterfly ----
    float cxx = wgt*dcx*dcx, cxy = wgt*dcx*dcy, cxz = wgt*dcx*dcz;
    float cyy = wgt*dcy*dcy, cyz = wgt*dcy*dcz, czz = wgt*dcz*dcz;
#pragma unroll
    for (int s = 16; s > 0; s >>= 1) {
        cxx += __shfl_xor_sync(FULLMASK, cxx, s);
        cxy += __shfl_xor_sync(FULLMASK, cxy, s);
        cxz += __shfl_xor_sync(FULLMASK, cxz, s);
        cyy += __shfl_xor_sync(FULLMASK, cyy, s);
        cyz += __shfl_xor_sync(FULLMASK, cyz, s);
        czz += __shfl_xor_sync(FULLMASK, czz, s);
    }

    if (lane == 0) {
        const float a00 = cxx + 1e-8f, a11 = cyy + 1e-8f, a22 = czz + 1e-8f;
        const float a01 = cxy, a02 = cxz, a12 = cyz;

        const float q = (a00 + a11 + a22) / 3.0f;
        const float b00 = a00 - q, b11 = a11 - q, b22 = a22 - q;
        const float ss = b00*b00 + b11*b11 + b22*b22
                       + 2.0f*(a01*a01 + a02*a02 + a12*a12);
        const float p = sqrtf(ss / 6.0f) + 1e-20f;

        const float B00 = b00/p, B11 = b11/p, B22 = b22/p;
        const float B01 = a01/p, B02 = a02/p, B12 = a12/p;
        const float det = B00*(B11*B22 - B12*B12)
                        - B01*(B01*B22 - B12*B02)
                        + B02*(B01*B12 - B11*B02);
        float r = det / 2.0f;
        r = fminf(fmaxf(r, -1.0f + 1e-7f), 1.0f - 1e-7f);
        const float phi = acosf(r) / 3.0f;
        const float e1 = q + 2.0f*p*cosf(phi);
        const float e3 = q + 2.0f*p*cosf(phi + 2.0943951023931953f);
        const float e2 = 3.0f*q - e1 - e3;

        float lam = e1, ab = fabsf(e1);
        if (fabsf(e2) < ab) { lam = e2; ab = fabsf(e2); }
        if (fabsf(e3) < ab) { lam = e3; }

        const float m00 = a00 - lam, m11 = a11 - lam, m22 = a22 - lam;
        const float c0x = a01*a12 - a02*m11;
        const float c0y = a02*a01 - m00*a12;
        const float c0z = m00*m11 - a01*a01;
        const float c1x = m11*m22 - a12*a12;
        const float c1y = a12*a02 - a01*m22;
        const float c1z = a01*a12 - m11*a02;
        const float c2x = a12*a02 - m22*a01;
        const float c2y = m22*m00 - a02*a02;
        const float c2z = a02*a01 - a12*m00;

        const float n0 = sqrtf(c0x*c0x + c0y*c0y + c0z*c0z);
        const float n1 = sqrtf(c1x*c1x + c1y*c1y + c1z*c1z);
        const float n2 = sqrtf(c2x*c2x + c2y*c2y + c2z*c2z);

        float vx = c0x, vy = c0y, vz = c0z, bn = n0;
        if (n1 > bn) { vx = c1x; vy = c1y; vz = c1z; bn = n1; }
        if (n2 > bn) { vx = c2x; vy = c2y; vz = c2z; }

        const float nv = sqrtf(vx*vx + vy*vy + vz*vz) + 1e-12f;
        out_normals[3*i+0] = vx / nv;
        out_normals[3*i+1] = vy / nv;
        out_normals[3*i+2] = vz / nv;
    }
}

extern "C" void kernel_launch(void* const* d_in, const int* in_sizes, int n_in,
                              void* d_out, int out_size)
{
    const float* old_w   = (const float*)d_in[0];   // (N,32)
    const float* pos     = (const float*)d_in[1];   // (N,3)
    const float* normals = (const float*)d_in[3];   // (N,3)
    const int*   dense_l = (const int*)d_in[5];     // (N,32)
    const float* stddev  = (const float*)d_in[6];   // (N,1)
    const float* W1      = (const float*)d_in[7];   // (7,32)
    const float* b1      = (const float*)d_in[8];   // (32,)
    const float* W2      = (const float*)d_in[9];   // (64,32)
    const float* b2      = (const float*)d_in[10];  // (32,)
    const float* W3      = (const float*)d_in[11];  // (32,1)
    const float* b3      = (const float*)d_in[12];  // (1,)

    const int N = in_sizes[1] / 3;

    // weights -> constant memory (byte-identical layout, viewed as packed pairs)
    cudaMemcpyToSymbolAsync(cW1p, W1, 7 * 32 * sizeof(float), 0, cudaMemcpyDeviceToDevice);
    cudaMemcpyToSymbolAsync(cB1p, b1, 32 * sizeof(float),     0, cudaMemcpyDeviceToDevice);
    cudaMemcpyToSymbolAsync(cW2p, W2, 64 * 32 * sizeof(float),0, cudaMemcpyDeviceToDevice);
    cudaMemcpyToSymbolAsync(cW3s, W3, 32 * sizeof(float),     0, cudaMemcpyDeviceToDevice);
    cudaMemcpyToSymbolAsync(cB3,  b3, sizeof(float),          0, cudaMemcpyDeviceToDevice);

    float* out         = (float*)d_out;
    float* out_normals = out;
    float* out_weights = out + (size_t)N * 3;

    pack_kernel<<<(N + 255) / 256, 256>>>(pos, normals, stddev, N);

    dim3 block(256);
    dim3 grid((N + 7) / 8);
    normal_est_kernel<<<grid, block>>>(old_w, dense_l, W2, b2,
                                       out_normals, out_weights, N);
}

// round 5
// speedup vs baseline: 1.3348x; 1.3348x over previous
#include <cuda_runtime.h>

#define FULLMASK 0xffffffffu

// ---- weights in constant memory (uniform LDCU path, off the L1 pipe) ----
__constant__ float cW1[7 * 32];
__constant__ float cB1[32];
__constant__ float cW2[64 * 32];
__constant__ float cB2[32];
__constant__ float cW3[32];
__constant__ float cB3[1];

// ---- packed per-point data: [pos.xyz, stddev][norm.xyz, 0] = one 32B sector ----
__device__ float4 g_packed[2 * 50048];

__global__ __launch_bounds__(256) void pack_kernel(
    const float* __restrict__ pos,
    const float* __restrict__ normals,
    const float* __restrict__ stddev,
    int N)
{
    int i = blockIdx.x * 256 + threadIdx.x;
    if (i >= N) return;
    float4 a, b;
    a.x = pos[3*i+0]; a.y = pos[3*i+1]; a.z = pos[3*i+2]; a.w = stddev[i];
    b.x = normals[3*i+0]; b.y = normals[3*i+1]; b.z = normals[3*i+2]; b.w = 0.0f;
    g_packed[2*i+0] = a;
    g_packed[2*i+1] = b;
}

// stride-36 rows: 144B = 16B aligned, conflict-free for both scalar STS (lane-major)
// and LDS.128 row reads (per quarter-warp phase, banks 4l..4l+3 are distinct).
#define PAD 36

__global__ __launch_bounds__(256, 4) void normal_est_kernel(
    const float* __restrict__ old_w,    // N*32
    const int*   __restrict__ dense_l,  // N*32
    const float* __restrict__ W2g,      // (64,32) global, for sW2bT fill
    float* __restrict__ out_normals,    // N*3
    float* __restrict__ out_weights,    // N*32
    int N)
{
    __shared__ __align__(16) float sH[8][32][PAD];   // per-warp h transpose
    __shared__ __align__(16) float sW2bT[32][PAD];   // [j][m] = W2[32+m][j]
    __shared__ __align__(16) float sG[8][32];
    __shared__ __align__(16) float sGw[8][32];

    const int tid  = threadIdx.x;
    const int lane = tid & 31;
    const int warp = tid >> 5;

    // cooperative fill of the lane-indexed half of W2 (can't be constant-indexed)
    for (int idx = tid; idx < 1024; idx += 256) {
        int m = idx >> 5, j = idx & 31;            // W2 row (32+m), col j
        sW2bT[j][m] = W2g[(32 + m) * 32 + j];
    }
    __syncthreads();

    const int i = blockIdx.x * 8 + warp;
    if (i >= N) return;

    // ---- gather (packed: 2 LDG.128 per neighbor, 1 sector) ----
    const int nb = dense_l[i * 32 + lane];

    const float4 ci = g_packed[2*i+0];     // broadcast
    const float4 ni = g_packed[2*i+1];     // broadcast
    const float4 cj = g_packed[2*nb+0];    // scattered
    const float4 nj = g_packed[2*nb+1];    // scattered

    const float dcx = cj.x - ci.x, dcy = cj.y - ci.y, dcz = cj.z - ci.z;
    const float invsd = 1.0f / ci.w;
    const float dx = dcx * invsd, dy = dcy * invsd, dz = dcz * invsd;
    const float wo = old_w[i * 32 + lane];
    const float f4 = fabsf(dx*ni.x + dy*ni.y + dz*ni.z);
    const float f5 = fabsf(dx*nj.x + dy*nj.y + dz*nj.z);
    const float f6 = fabsf(ni.x*nj.x + ni.y*nj.y + ni.z*nj.z);

    float f[7];
    f[0] = dx; f[1] = dy; f[2] = dz; f[3] = wo; f[4] = f4; f[5] = f5; f[6] = f6;

    // ---- layer 1: h = relu(f @ W1 + b1)  (constant-port weight loads) ----
    float h[32];
#pragma unroll
    for (int j = 0; j < 32; j += 4) {
        const float4 bv = *(const float4*)&cB1[j];
        h[j+0] = bv.x; h[j+1] = bv.y; h[j+2] = bv.z; h[j+3] = bv.w;
    }
#pragma unroll
    for (int in = 0; in < 7; ++in) {
        const float fv = f[in];
#pragma unroll
        for (int j = 0; j < 32; j += 4) {
            const float4 wv = *(const float4*)&cW1[in * 32 + j];
            h[j+0] = fmaf(fv, wv.x, h[j+0]);
            h[j+1] = fmaf(fv, wv.y, h[j+1]);
            h[j+2] = fmaf(fv, wv.z, h[j+2]);
            h[j+3] = fmaf(fv, wv.w, h[j+3]);
        }
    }
#pragma unroll
    for (int j = 0; j < 32; ++j) h[j] = fmaxf(h[j], 0.0f);

    // ---- segment max via shared transpose (vectorized read) ----
#pragma unroll
    for (int j = 0; j < 32; ++j) sH[warp][j][lane] = h[j];
    __syncwarp();
    float g;
    {
        const float4* row = (const float4*)&sH[warp][lane][0];
        float4 v0 = row[0];
        float m0 = fmaxf(fmaxf(v0.x, v0.y), fmaxf(v0.z, v0.w));
#pragma unroll
        for (int e = 1; e < 8; ++e) {
            const float4 v = row[e];
            m0 = fmaxf(m0, fmaxf(fmaxf(v.x, v.y), fmaxf(v.z, v.w)));
        }
        g = m0;
    }

    // ---- shared half of layer 2: gw = b2 + g @ W2[32:64]  (once/point) ----
    sG[warp][lane] = g;
    __syncwarp();
    float gw = cB2[lane];
    {
        const float4* grow = (const float4*)&sG[warp][0];       // broadcast
        const float4* wrow = (const float4*)&sW2bT[lane][0];    // per-lane row
#pragma unroll
        for (int q = 0; q < 8; ++q) {
            const float4 gv = grow[q];
            const float4 wv = wrow[q];
            gw = fmaf(gv.x, wv.x, gw);
            gw = fmaf(gv.y, wv.y, gw);
            gw = fmaf(gv.z, wv.z, gw);
            gw = fmaf(gv.w, wv.w, gw);
        }
    }
    sGw[warp][lane] = gw;
    __syncwarp();

    // ---- layer 2 per-edge + layer 3, split into two j-halves of 16
    //      (halves live registers: h[32] + acc[16] instead of h[32] + h2[32]) ----
    float s3 = 0.0f;
#pragma unroll
    for (int jh = 0; jh < 2; ++jh) {
        float acc[16];
        const float4* gv4 = (const float4*)&sGw[warp][jh * 16];
#pragma unroll
        for (int q = 0; q < 4; ++q) {
            const float4 gv = gv4[q];                 // broadcast LDS.128
            acc[4*q+0] = gv.x; acc[4*q+1] = gv.y; acc[4*q+2] = gv.z; acc[4*q+3] = gv.w;
        }
#pragma unroll
        for (int m = 0; m < 32; ++m) {
            const float hm = h[m];
#pragma unroll
            for (int k = 0; k < 16; k += 4) {
                const float4 wv = *(const float4*)&cW2[m * 32 + jh * 16 + k];
                acc[k+0] = fmaf(hm, wv.x, acc[k+0]);
                acc[k+1] = fmaf(hm, wv.y, acc[k+1]);
                acc[k+2] = fmaf(hm, wv.z, acc[k+2]);
                acc[k+3] = fmaf(hm, wv.w, acc[k+3]);
            }
        }
#pragma unroll
        for (int k = 0; k < 16; k += 4) {
            const float4 w3v = *(const float4*)&cW3[jh * 16 + k];
            s3 = fmaf(fmaxf(acc[k+0], 0.0f), w3v.x, s3);
            s3 = fmaf(fmaxf(acc[k+1], 0.0f), w3v.y, s3);
            s3 = fmaf(fmaxf(acc[k+2], 0.0f), w3v.z, s3);
            s3 = fmaf(fmaxf(acc[k+3], 0.0f), w3v.w, s3);
        }
    }
    const float wgt = 1.0f / (1.0f + __expf(-(s3 + cB3[0])));

    out_weights[i * 32 + lane] = wgt;

    // ---- weighted covariance (unscaled dc), 6-term butterfly ----
    float cxx = wgt*dcx*dcx, cxy = wgt*dcx*dcy, cxz = wgt*dcx*dcz;
    float cyy = wgt*dcy*dcy, cyz = wgt*dcy*dcz, czz = wgt*dcz*dcz;
#pragma unroll
    for (int s = 16; s > 0; s >>= 1) {
        cxx += __shfl_xor_sync(FULLMASK, cxx, s);
        cxy += __shfl_xor_sync(FULLMASK, cxy, s);
        cxz += __shfl_xor_sync(FULLMASK, cxz, s);
        cyy += __shfl_xor_sync(FULLMASK, cyy, s);
        cyz += __shfl_xor_sync(FULLMASK, cyz, s);
        czz += __shfl_xor_sync(FULLMASK, czz, s);
    }

    if (lane == 0) {
        const float a00 = cxx + 1e-8f, a11 = cyy + 1e-8f, a22 = czz + 1e-8f;
        const float a01 = cxy, a02 = cxz, a12 = cyz;

        const float q = (a00 + a11 + a22) / 3.0f;
        const float b00 = a00 - q, b11 = a11 - q, b22 = a22 - q;
        const float ss = b00*b00 + b11*b11 + b22*b22
                       + 2.0f*(a01*a01 + a02*a02 + a12*a12);
        const float p = sqrtf(ss / 6.0f) + 1e-20f;

        const float B00 = b00/p, B11 = b11/p, B22 = b22/p;
        const float B01 = a01/p, B02 = a02/p, B12 = a12/p;
        const float det = B00*(B11*B22 - B12*B12)
                        - B01*(B01*B22 - B12*B02)
                        + B02*(B01*B12 - B11*B02);
        float r = det / 2.0f;
        r = fminf(fmaxf(r, -1.0f + 1e-7f), 1.0f - 1e-7f);
        const float phi = acosf(r) / 3.0f;
        const float e1 = q + 2.0f*p*cosf(phi);
        const float e3 = q + 2.0f*p*cosf(phi + 2.0943951023931953f);
        const float e2 = 3.0f*q - e1 - e3;

        float lam = e1, ab = fabsf(e1);
        if (fabsf(e2) < ab) { lam = e2; ab = fabsf(e2); }
        if (fabsf(e3) < ab) { lam = e3; }

        const float m00 = a00 - lam, m11 = a11 - lam, m22 = a22 - lam;
        const float c0x = a01*a12 - a02*m11;
        const float c0y = a02*a01 - m00*a12;
        const float c0z = m00*m11 - a01*a01;
        const float c1x = m11*m22 - a12*a12;
        const float c1y = a12*a02 - a01*m22;
        const float c1z = a01*a12 - m11*a02;
        const float c2x = a12*a02 - m22*a01;
        const float c2y = m22*m00 - a02*a02;
        const float c2z = a02*a01 - a12*m00;

        const float n0 = sqrtf(c0x*c0x + c0y*c0y + c0z*c0z);
        const float n1 = sqrtf(c1x*c1x + c1y*c1y + c1z*c1z);
        const float n2 = sqrtf(c2x*c2x + c2y*c2y + c2z*c2z);

        float vx = c0x, vy = c0y, vz = c0z, bn = n0;
        if (n1 > bn) { vx = c1x; vy = c1y; vz = c1z; bn = n1; }
        if (n2 > bn) { vx = c2x; vy = c2y; vz = c2z; }

        const float nv = sqrtf(vx*vx + vy*vy + vz*vz) + 1e-12f;
        out_normals[3*i+0] = vx / nv;
        out_normals[3*i+1] = vy / nv;
        out_normals[3*i+2] = vz / nv;
    }
}

extern "C" void kernel_launch(void* const* d_in, const int* in_sizes, int n_in,
                              void* d_out, int out_size)
{
    const float* old_w   = (const float*)d_in[0];   // (N,32)
    const float* pos     = (const float*)d_in[1];   // (N,3)
    const float* normals = (const float*)d_in[3];   // (N,3)
    const int*   dense_l = (const int*)d_in[5];     // (N,32)
    const float* stddev  = (const float*)d_in[6];   // (N,1)
    const float* W1      = (const float*)d_in[7];   // (7,32)
    const float* b1      = (const float*)d_in[8];   // (32,)
    const float* W2      = (const float*)d_in[9];   // (64,32)
    const float* b2      = (const float*)d_in[10];  // (32,)
    const float* W3      = (const float*)d_in[11];  // (32,1)
    const float* b3      = (const float*)d_in[12];  // (1,)

    const int N = in_sizes[1] / 3;

    cudaMemcpyToSymbolAsync(cW1, W1, 7 * 32 * sizeof(float), 0, cudaMemcpyDeviceToDevice);
    cudaMemcpyToSymbolAsync(cB1, b1, 32 * sizeof(float),     0, cudaMemcpyDeviceToDevice);
    cudaMemcpyToSymbolAsync(cW2, W2, 64 * 32 * sizeof(float),0, cudaMemcpyDeviceToDevice);
    cudaMemcpyToSymbolAsync(cB2, b2, 32 * sizeof(float),     0, cudaMemcpyDeviceToDevice);
    cudaMemcpyToSymbolAsync(cW3, W3, 32 * sizeof(float),     0, cudaMemcpyDeviceToDevice);
    cudaMemcpyToSymbolAsync(cB3, b3, sizeof(float),          0, cudaMemcpyDeviceToDevice);

    float* out         = (float*)d_out;
    float* out_normals = out;
    float* out_weights = out + (size_t)N * 3;

    pack_kernel<<<(N + 255) / 256, 256>>>(pos, normals, stddev, N);

    dim3 block(256);
    dim3 grid((N + 7) / 8);
    normal_est_kernel<<<grid, block>>>(old_w, dense_l, W2,
                                       out_normals, out_weights, N);
}

// round 7
// speedup vs baseline: 1.5812x; 1.1846x over previous
#include <cuda_runtime.h>

#define FULLMASK 0xffffffffu

// ---- weights in constant memory ----
__constant__ float cW1[7 * 32];
__constant__ float cB1[32];
__constant__ float cB2[32];
__constant__ float cW3[32];
__constant__ float cB3[1];

// ---- packed per-point data: [pos.xyz, stddev][norm.xyz, 0] ----
__device__ float4 g_packed[2 * 50048];

__global__ __launch_bounds__(256) void pack_kernel(
    const float* __restrict__ pos,
    const float* __restrict__ normals,
    const float* __restrict__ stddev,
    int N)
{
    int i = blockIdx.x * 256 + threadIdx.x;
    if (i >= N) return;
    float4 a, b;
    a.x = pos[3*i+0]; a.y = pos[3*i+1]; a.z = pos[3*i+2]; a.w = stddev[i];
    b.x = normals[3*i+0]; b.y = normals[3*i+1]; b.z = normals[3*i+2]; b.w = 0.0f;
    g_packed[2*i+0] = a;
    g_packed[2*i+1] = b;
}

__device__ __forceinline__ unsigned f2tf32(float f) {
    unsigned r; asm("cvt.rna.tf32.f32 %0, %1;" : "=r"(r) : "f"(f)); return r;
}
__device__ __forceinline__ void mma8(float& d0, float& d1, float& d2, float& d3,
                                     unsigned a0, unsigned a1, unsigned a2, unsigned a3,
                                     unsigned b0, unsigned b1) {
    asm volatile(
        "mma.sync.aligned.m16n8k8.row.col.f32.tf32.tf32.f32 "
        "{%0,%1,%2,%3}, {%4,%5,%6,%7}, {%8,%9}, {%0,%1,%2,%3};"
        : "+f"(d0), "+f"(d1), "+f"(d2), "+f"(d3)
        : "r"(a0), "r"(a1), "r"(a2), "r"(a3), "r"(b0), "r"(b1));
}

__global__ __launch_bounds__(256, 4) void normal_est_kernel(
    const float* __restrict__ old_w,    // N*32
    const int*   __restrict__ dense_l,  // N*32
    const float* __restrict__ W2g,      // (64,32)
    float* __restrict__ out_normals,
    float* __restrict__ out_weights,
    int N)
{
    __shared__ __align__(16) float    sH[8][32][36];   // per-warp h rows (fp32)
    __shared__            unsigned    sW2f[32][40];    // W2 rows 0..31 as tf32 (B matrix)
    __shared__ __align__(16) float    sW2bT[32][36];   // [j][m] = W2[32+m][j]
    __shared__ __align__(16) float    sG[8][32];       // g, later reused for wgt
    __shared__ __align__(16) float    sGw[8][32];
    __shared__            float       sW3s[32];

    const int tid  = threadIdx.x;
    const int lane = tid & 31;
    const int warp = tid >> 5;
    const int lp   = lane & 3;      // quad-lane
    const int lq   = lane >> 2;     // quad-row

    for (int idx = tid; idx < 1024; idx += 256) {
        int m = idx >> 5, j = idx & 31;
        sW2bT[j][m] = W2g[(32 + m) * 32 + j];
    }
    for (int idx = tid; idx < 1024; idx += 256) {
        int m = idx >> 5, j = idx & 31;
        sW2f[m][j] = f2tf32(W2g[m * 32 + j]);
    }
    if (tid < 32) sW3s[tid] = cW3[tid];
    __syncthreads();

    const int i = blockIdx.x * 8 + warp;
    if (i >= N) return;

    // ---- gather ----
    const int nb = dense_l[i * 32 + lane];
    const float4 ci = g_packed[2*i+0];
    const float4 ni = g_packed[2*i+1];
    const float4 cj = g_packed[2*nb+0];
    const float4 nj = g_packed[2*nb+1];

    const float dcx = cj.x - ci.x, dcy = cj.y - ci.y, dcz = cj.z - ci.z;
    const float invsd = 1.0f / ci.w;
    const float dx = dcx * invsd, dy = dcy * invsd, dz = dcz * invsd;
    const float wo = old_w[i * 32 + lane];
    const float f4 = fabsf(dx*ni.x + dy*ni.y + dz*ni.z);
    const float f5 = fabsf(dx*nj.x + dy*nj.y + dz*nj.z);
    const float f6 = fabsf(ni.x*nj.x + ni.y*nj.y + ni.z*nj.z);
    float f[7];
    f[0] = dx; f[1] = dy; f[2] = dz; f[3] = wo; f[4] = f4; f[5] = f5; f[6] = f6;

    // ---- layer 1 (constant port) ----
    {
        float h[32];
#pragma unroll
        for (int j = 0; j < 32; j += 4) {
            const float4 bv = *(const float4*)&cB1[j];
            h[j+0] = bv.x; h[j+1] = bv.y; h[j+2] = bv.z; h[j+3] = bv.w;
        }
#pragma unroll
        for (int in = 0; in < 7; ++in) {
            const float fv = f[in];
#pragma unroll
            for (int j = 0; j < 32; j += 4) {
                const float4 wv = *(const float4*)&cW1[in * 32 + j];
                h[j+0] = fmaf(fv, wv.x, h[j+0]);
                h[j+1] = fmaf(fv, wv.y, h[j+1]);
                h[j+2] = fmaf(fv, wv.z, h[j+2]);
                h[j+3] = fmaf(fv, wv.w, h[j+3]);
            }
        }
        // store my edge-row (fp32, post-relu) into sH
        float* hrow = &sH[warp][lane][0];
#pragma unroll
        for (int q = 0; q < 8; ++q) {
            float4 v;
            v.x = fmaxf(h[4*q+0], 0.0f); v.y = fmaxf(h[4*q+1], 0.0f);
            v.z = fmaxf(h[4*q+2], 0.0f); v.w = fmaxf(h[4*q+3], 0.0f);
            ((float4*)hrow)[q] = v;
        }
    }
    __syncwarp();

    // ---- segment max: lane j maxes column j over 32 rows ----
    float g = sH[warp][0][lane];
#pragma unroll
    for (int e = 1; e < 32; ++e) g = fmaxf(g, sH[warp][e][lane]);
    sG[warp][lane] = g;
    __syncwarp();

    // ---- gw = b2 + g @ W2[32:64]  (fp32, once per point) ----
    float gw = cB2[lane];
    {
        const float4* grow = (const float4*)&sG[warp][0];
        const float4* wrow = (const float4*)&sW2bT[lane][0];
#pragma unroll
        for (int q = 0; q < 8; ++q) {
            const float4 gv = grow[q], wv = wrow[q];
            gw = fmaf(gv.x, wv.x, gw); gw = fmaf(gv.y, wv.y, gw);
            gw = fmaf(gv.z, wv.z, gw); gw = fmaf(gv.w, wv.w, gw);
        }
    }
    sGw[warp][lane] = gw;
    __syncwarp();

    // ---- layer 2 on tensor pipe: [32x32] = [32x32 h] @ [32x32 W2a], tf32 mma ----
    float s3p[4] = {0.0f, 0.0f, 0.0f, 0.0f};   // rows lq, lq+8, lq+16, lq+24
#pragma unroll
    for (int mt = 0; mt < 2; ++mt) {
        unsigned a[16];
#pragma unroll
        for (int kt = 0; kt < 4; ++kt) {
            a[kt*4+0] = f2tf32(sH[warp][mt*16 + lq    ][kt*8 + lp    ]);
            a[kt*4+1] = f2tf32(sH[warp][mt*16 + lq + 8][kt*8 + lp    ]);
            a[kt*4+2] = f2tf32(sH[warp][mt*16 + lq    ][kt*8 + lp + 4]);
            a[kt*4+3] = f2tf32(sH[warp][mt*16 + lq + 8][kt*8 + lp + 4]);
        }
#pragma unroll
        for (int nt = 0; nt < 4; ++nt) {
            float d0 = 0.0f, d1 = 0.0f, d2 = 0.0f, d3 = 0.0f;
#pragma unroll
            for (int kt = 0; kt < 4; ++kt) {
                const unsigned b0 = sW2f[kt*8 + lp    ][nt*8 + lq];
                const unsigned b1 = sW2f[kt*8 + lp + 4][nt*8 + lq];
                mma8(d0, d1, d2, d3,
                     a[kt*4+0], a[kt*4+1], a[kt*4+2], a[kt*4+3], b0, b1);
            }
            const int c0 = nt*8 + 2*lp;
            const float2 gv = *(const float2*)&sGw[warp][c0];
            const float2 wv = *(const float2*)&sW3s[c0];
            s3p[mt*2+0] = fmaf(fmaxf(d0 + gv.x, 0.0f), wv.x, s3p[mt*2+0]);
            s3p[mt*2+0] = fmaf(fmaxf(d1 + gv.y, 0.0f), wv.y, s3p[mt*2+0]);
            s3p[mt*2+1] = fmaf(fmaxf(d2 + gv.x, 0.0f), wv.x, s3p[mt*2+1]);
            s3p[mt*2+1] = fmaf(fmaxf(d3 + gv.y, 0.0f), wv.y, s3p[mt*2+1]);
        }
    }
    // quad reduction: sum the 4 column-partials of each row
#pragma unroll
    for (int k = 0; k < 4; ++k) {
        s3p[k] += __shfl_xor_sync(FULLMASK, s3p[k], 1);
        s3p[k] += __shfl_xor_sync(FULLMASK, s3p[k], 2);
    }
    // rows for this quad: lq, lq+8, lq+16, lq+24 (order mt0:{lq,lq+8}, mt1:{+16,+24})
    float wr[4];
#pragma unroll
    for (int k = 0; k < 4; ++k)
        wr[k] = 1.0f / (1.0f + __expf(-(s3p[k] + cB3[0])));
    if (lp == 0) {
        sG[warp][lq     ] = wr[0];
        sG[warp][lq +  8] = wr[1];
        sG[warp][lq + 16] = wr[2];
        sG[warp][lq + 24] = wr[3];
    }
    __syncwarp();
    const float wgt = sG[warp][lane];

    out_weights[i * 32 + lane] = wgt;

    // ---- weighted covariance (unscaled dc), 6-term butterfly ----
    float cxx = wgt*dcx*dcx, cxy = wgt*dcx*dcy, cxz = wgt*dcx*dcz;
    float cyy = wgt*dcy*dcy, cyz = wgt*dcy*dcz, czz = wgt*dcz*dcz;
#pragma unroll
    for (int s = 16; s > 0; s >>= 1) {
        cxx += __shfl_xor_sync(FULLMASK, cxx, s);
        cxy += __shfl_xor_sync(FULLMASK, cxy, s);
        cxz += __shfl_xor_sync(FULLMASK, cxz, s);
        cyy += __shfl_xor_sync(FULLMASK, cyy, s);
        cyz += __shfl_xor_sync(FULLMASK, cyz, s);
        czz += __shfl_xor_sync(FULLMASK, czz, s);
    }

    if (lane == 0) {
        const float a00 = cxx + 1e-8f, a11 = cyy + 1e-8f, a22 = czz + 1e-8f;
        const float a01 = cxy, a02 = cxz, a12 = cyz;

        const float q = (a00 + a11 + a22) / 3.0f;
        const float b00 = a00 - q, b11 = a11 - q, b22 = a22 - q;
        const float ss = b00*b00 + b11*b11 + b22*b22
                       + 2.0f*(a01*a01 + a02*a02 + a12*a12);
        const float p = sqrtf(ss / 6.0f) + 1e-20f;

        const float B00 = b00/p, B11 = b11/p, B22 = b22/p;
        const float B01 = a01/p, B02 = a02/p, B12 = a12/p;
        const float det = B00*(B11*B22 - B12*B12)
                        - B01*(B01*B22 - B12*B02)
                        + B02*(B01*B12 - B11*B02);
        float r = det / 2.0f;
        r = fminf(fmaxf(r, -1.0f + 1e-7f), 1.0f - 1e-7f);
        const float phi = acosf(r) / 3.0f;
        const float e1 = q + 2.0f*p*cosf(phi);
        const float e3 = q + 2.0f*p*cosf(phi + 2.0943951023931953f);
        const float e2 = 3.0f*q - e1 - e3;

        float lam = e1, ab = fabsf(e1);
        if (fabsf(e2) < ab) { lam = e2; ab = fabsf(e2); }
        if (fabsf(e3) < ab) { lam = e3; }

        const float m00 = a00 - lam, m11 = a11 - lam, m22 = a22 - lam;
        const float c0x = a01*a12 - a02*m11;
        const float c0y = a02*a01 - m00*a12;
        const float c0z = m00*m11 - a01*a01;
        const float c1x = m11*m22 - a12*a12;
        const float c1y = a12*a02 - a01*m22;
        const float c1z = a01*a12 - m11*a02;
        const float c2x = a12*a02 - m22*a01;
        const float c2y = m22*m00 - a02*a02;
        const float c2z = a02*a01 - a12*m00;

        const float n0 = sqrtf(c0x*c0x + c0y*c0y + c0z*c0z);
        const float n1 = sqrtf(c1x*c1x + c1y*c1y + c1z*c1z);
        const float n2 = sqrtf(c2x*c2x + c2y*c2y + c2z*c2z);

        float vx = c0x, vy = c0y, vz = c0z, bn = n0;
        if (n1 > bn) { vx = c1x; vy = c1y; vz = c1z; bn = n1; }
        if (n2 > bn) { vx = c2x; vy = c2y; vz = c2z; }

        const float nv = sqrtf(vx*vx + vy*vy + vz*vz) + 1e-12f;
        out_normals[3*i+0] = vx / nv;
        out_normals[3*i+1] = vy / nv;
        out_normals[3*i+2] = vz / nv;
    }
}

extern "C" void kernel_launch(void* const* d_in, const int* in_sizes, int n_in,
                              void* d_out, int out_size)
{
    const float* old_w   = (const float*)d_in[0];
    const float* pos     = (const float*)d_in[1];
    const float* normals = (const float*)d_in[3];
    const int*   dense_l = (const int*)d_in[5];
    const float* stddev  = (const float*)d_in[6];
    const float* W1      = (const float*)d_in[7];
    const float* b1      = (const float*)d_in[8];
    const float* W2      = (const float*)d_in[9];
    const float* b2      = (const float*)d_in[10];
    const float* W3      = (const float*)d_in[11];
    const float* b3      = (const float*)d_in[12];

    const int N = in_sizes[1] / 3;

    cudaMemcpyToSymbolAsync(cW1, W1, 7 * 32 * sizeof(float), 0, cudaMemcpyDeviceToDevice);
    cudaMemcpyToSymbolAsync(cB1, b1, 32 * sizeof(float),     0, cudaMemcpyDeviceToDevice);
    cudaMemcpyToSymbolAsync(cB2, b2, 32 * sizeof(float),     0, cudaMemcpyDeviceToDevice);
    cudaMemcpyToSymbolAsync(cW3, W3, 32 * sizeof(float),     0, cudaMemcpyDeviceToDevice);
    cudaMemcpyToSymbolAsync(cB3, b3, sizeof(float),          0, cudaMemcpyDeviceToDevice);

    float* out         = (float*)d_out;
    float* out_normals = out;
    float* out_weights = out + (size_t)N * 3;

    pack_kernel<<<(N + 255) / 256, 256>>>(pos, normals, stddev, N);

    dim3 block(256);
    dim3 grid((N + 7) / 8);
    normal_est_kernel<<<grid, block>>>(old_w, dense_l, W2,
                                       out_normals, out_weights, N);
}